// round 4
// baseline (speedup 1.0000x reference)
#include <cuda_runtime.h>

// Problem constants
#define NN 50000
#define EE 800000
#define NH 64
#define NGR 500

// Scratch (device globals; no allocation allowed)
__device__ __align__(16) float g_X[NN * NH];
__device__ __align__(16) float g_Y[NN * NH];
__device__ __align__(16) float g_hW[NN * NH];
__device__ __align__(16) float g_agg[NN * NH];
__device__ float g_deg[NN];
__device__ float g_dinv[NN];
__device__ float g_norm[EE];
__device__ int   g_src[EE];
__device__ int   g_dst[EE];

// ---------------------------------------------------------------------------
// Graph-structure precompute (once per launch, reused over 5 layers)
// ---------------------------------------------------------------------------
__global__ void k_init_deg() {
    int n = blockIdx.x * 256 + threadIdx.x;
    if (n < NN) g_deg[n] = 1.0f;  // self-loop
}

__global__ void k_edge_prep(const int* __restrict__ ei) {
    int e = blockIdx.x * 256 + threadIdx.x;
    if (e >= EE) return;
    int s = ei[e];
    int d = ei[EE + e];
    g_src[e] = s;
    g_dst[e] = d;
    atomicAdd(&g_deg[d], 1.0f);
}

__global__ void k_dinv() {
    int n = blockIdx.x * 256 + threadIdx.x;
    if (n < NN) g_dinv[n] = rsqrtf(g_deg[n]);
}

__global__ void k_norm() {
    int e = blockIdx.x * 256 + threadIdx.x;
    if (e >= EE) return;
    g_norm[e] = g_dinv[g_src[e]] * g_dinv[g_dst[e]];
}

// ---------------------------------------------------------------------------
// Encoder: Y = X = concat(x, pos) @ enc_W + enc_b
// ---------------------------------------------------------------------------
__global__ void k_encoder(const float* __restrict__ x, const float* __restrict__ pos,
                          const float* __restrict__ encW, const float* __restrict__ encB) {
    __shared__ float Ws[16 * 64];
    int t = threadIdx.x;  // 256
    for (int i = t; i < 16 * 64; i += 256) Ws[i] = encW[i];
    __syncthreads();
    int c = t & 63;
    int n = blockIdx.x * 4 + (t >> 6);
    if (n >= NN) return;
    float acc = 0.0f;
#pragma unroll
    for (int f = 0; f < 14; f++) acc += x[n * 14 + f] * Ws[f * 64 + c];
    acc += pos[n * 2 + 0] * Ws[14 * 64 + c];
    acc += pos[n * 2 + 1] * Ws[15 * 64 + c];
    acc += encB[c];
    g_Y[n * 64 + c] = acc;
    g_X[n * 64 + c] = acc;
}

// ---------------------------------------------------------------------------
// Per-layer GEMM: hW = X@conv_W ; agg = hW*dinv^2 + X@res_W + conv_b + res_b
// 32 rows per block, 256 threads; each thread: 1 col x 8 rows x 2 matrices
// ---------------------------------------------------------------------------
__global__ void k_layer_gemm(const float* __restrict__ convW, const float* __restrict__ convB,
                             const float* __restrict__ resW, const float* __restrict__ resB) {
    __shared__ float Xs[32][64];
    __shared__ float Wc[64][64];
    __shared__ float Wr[64][64];
    int t = threadIdx.x;  // 256
    int row0 = blockIdx.x * 32;
    for (int i = t; i < 64 * 64; i += 256) {
        Wc[i >> 6][i & 63] = convW[i];
        Wr[i >> 6][i & 63] = resW[i];
    }
    for (int i = t; i < 32 * 64; i += 256) {
        int r = i >> 6, k = i & 63;
        int n = row0 + r;
        if (n >= NN) n = NN - 1;  // clamp, discarded on store
        Xs[r][k] = g_X[n * 64 + k];
    }
    __syncthreads();
    int c = t & 63;
    int rg = t >> 6;  // 0..3 (8 rows each)
    float accC[8], accR[8];
#pragma unroll
    for (int r = 0; r < 8; r++) { accC[r] = 0.0f; accR[r] = 0.0f; }
#pragma unroll
    for (int k = 0; k < 64; k++) {
        float wc = Wc[k][c];
        float wr = Wr[k][c];
#pragma unroll
        for (int r = 0; r < 8; r++) {
            float xv = Xs[rg * 8 + r][k];
            accC[r] += xv * wc;
            accR[r] += xv * wr;
        }
    }
    float bias = convB[c] + resB[c];
#pragma unroll
    for (int r = 0; r < 8; r++) {
        int n = row0 + rg * 8 + r;
        if (n < NN) {
            float dv = g_dinv[n];
            float hw = accC[r];
            g_hW[n * 64 + c] = hw;
            g_agg[n * 64 + c] = hw * (dv * dv) + accR[r] + bias;
        }
    }
}

// ---------------------------------------------------------------------------
// Edge scatter: agg[dst] += hW[src] * norm[e]   (16 threads x float4 per edge)
// ---------------------------------------------------------------------------
__global__ void k_edge_scatter() {
    int idx = blockIdx.x * 256 + threadIdx.x;
    int e = idx >> 4;
    if (e >= EE) return;
    int lane = idx & 15;
    int s = __ldg(&g_src[e]);
    int d = __ldg(&g_dst[e]);
    float nrm = __ldg(&g_norm[e]);
    const float4 v = *(const float4*)&g_hW[s * 64 + lane * 4];
    float m0 = v.x * nrm, m1 = v.y * nrm, m2 = v.z * nrm, m3 = v.w * nrm;
    float* p = &g_agg[d * 64 + lane * 4];
    asm volatile("red.global.add.v4.f32 [%0], {%1, %2, %3, %4};"
                 :: "l"(p), "f"(m0), "f"(m1), "f"(m2), "f"(m3)
                 : "memory");
}

// ---------------------------------------------------------------------------
// Elementwise: Y = Y + (relu(agg) - Y - X); X = X + Y
// ---------------------------------------------------------------------------
__global__ void k_update_xy() {
    int i = blockIdx.x * 256 + threadIdx.x;
    if (i >= NN * NH) return;
    float a = g_agg[i];
    float y = g_Y[i];
    float xv = g_X[i];
    float r = fmaxf(a, 0.0f);
    float ynew = y + ((r - y) - xv);
    g_Y[i] = ynew;
    g_X[i] = xv + ynew;
}

// ---------------------------------------------------------------------------
// Decoder + pooling: out[batch[n]] += X[n]@dec_W + dec_b
// ---------------------------------------------------------------------------
__global__ void k_zero_out(float* __restrict__ out) {
    int i = blockIdx.x * 256 + threadIdx.x;
    if (i < NGR) out[i] = 0.0f;
}

__global__ void k_decode_pool(const float* __restrict__ decW, const float* __restrict__ decB,
                              const int* __restrict__ batch, float* __restrict__ out) {
    __shared__ float dw[64];
    int t = threadIdx.x;  // 256 = 8 warps, one node per warp
    if (t < 64) dw[t] = decW[t];
    __syncthreads();
    int lane = t & 31;
    int n = blockIdx.x * 8 + (t >> 5);
    if (n >= NN) return;
    float v = g_X[n * 64 + lane] * dw[lane] + g_X[n * 64 + lane + 32] * dw[lane + 32];
#pragma unroll
    for (int o = 16; o; o >>= 1) v += __shfl_xor_sync(0xffffffffu, v, o);
    if (lane == 0) atomicAdd(&out[batch[n]], v + decB[0]);
}

// ---------------------------------------------------------------------------
extern "C" void kernel_launch(void* const* d_in, const int* in_sizes, int n_in,
                              void* d_out, int out_size) {
    const float* x        = (const float*)d_in[0];
    const float* pos      = (const float*)d_in[1];
    const int*   ei       = (const int*)d_in[2];     // int32 (JAX x64 disabled)
    const int*   batch    = (const int*)d_in[3];     // int32
    const float* encW     = (const float*)d_in[4];
    const float* encB     = (const float*)d_in[5];
    const float* convW    = (const float*)d_in[6];
    const float* convB    = (const float*)d_in[7];
    const float* resW     = (const float*)d_in[8];
    const float* resB     = (const float*)d_in[9];
    const float* decW     = (const float*)d_in[10];
    const float* decB     = (const float*)d_in[11];
    float* out            = (float*)d_out;

    const int nb_n   = (NN + 255) / 256;
    const int nb_e   = (EE + 255) / 256;
    const int nb_enc = (NN + 3) / 4;
    const int nb_gem = (NN + 31) / 32;
    const int nb_sc  = (EE * 16 + 255) / 256;
    const int nb_el  = (NN * NH + 255) / 256;
    const int nb_dec = (NN + 7) / 8;

    k_zero_out<<<(NGR + 255) / 256, 256>>>(out);
    k_init_deg<<<nb_n, 256>>>();
    k_edge_prep<<<nb_e, 256>>>(ei);
    k_dinv<<<nb_n, 256>>>();
    k_norm<<<nb_e, 256>>>();
    k_encoder<<<nb_enc, 256>>>(x, pos, encW, encB);

    for (int layer = 0; layer < 5; layer++) {
        k_layer_gemm<<<nb_gem, 256>>>(convW, convB, resW, resB);
        k_edge_scatter<<<nb_sc, 256>>>();
        k_update_xy<<<nb_el, 256>>>();
    }

    k_decode_pool<<<nb_dec, 256>>>(decW, decB, batch, out);
}